// round 9
// baseline (speedup 1.0000x reference)
#include <cuda_runtime.h>
#include <math_constants.h>

#define H 4
#define C 32
#define HC 128
#define NEG_SLOPE 0.2f

#define N_TX_MAX 100000
#define N_BD_MAX 10000
#define E_ALL_MAX 2000000

// padded segmented CSR layout
#define SEG0 0
#define SEG1 102400
#define SEG2 204800
#define NPAD 215040
#define NBLK 210

// ---------------- device scratch ----------------
__device__ float g_xl_tt[(size_t)N_TX_MAX * HC];
__device__ float g_xr_tt[(size_t)N_TX_MAX * HC];
__device__ float g_xl_tb[(size_t)N_TX_MAX * HC];
__device__ float g_xr_bt[(size_t)N_TX_MAX * HC];
__device__ float g_xl_bt[(size_t)N_BD_MAX * HC];
__device__ float g_xr_tb[(size_t)N_BD_MAX * HC];

__device__ int g_cnt[NPAD];
__device__ int g_rowptr[NPAD];
__device__ int g_cursor[NPAD];
__device__ int g_bsums[1024];
__device__ int g_srcs[E_ALL_MAX];
__device__ int g_src64;

// ---------------- static stream/event setup (checked, with serial fallback) ----
struct ForkCtx {
    cudaStream_t s1 = nullptr;
    cudaEvent_t e0 = nullptr, e1 = nullptr;
    bool ok = false;
    ForkCtx() {
        if (cudaStreamCreateWithFlags(&s1, cudaStreamNonBlocking) != cudaSuccess) { s1 = nullptr; return; }
        if (cudaEventCreateWithFlags(&e0, cudaEventDisableTiming) != cudaSuccess) { e0 = nullptr; return; }
        if (cudaEventCreateWithFlags(&e1, cudaEventDisableTiming) != cudaSuccess) { e1 = nullptr; return; }
        ok = true;
    }
};
static ForkCtx g_fork;

// ---------------- packed f32x2 helpers ----------------
__device__ __forceinline__ unsigned long long pack_dup(float x) {
    unsigned long long r;
    asm("mov.b64 %0, {%1, %1};" : "=l"(r) : "f"(x));
    return r;
}
__device__ __forceinline__ void ffma2(unsigned long long& d,
                                      unsigned long long a,
                                      unsigned long long b) {
    asm("fma.rn.f32x2 %0, %1, %2, %0;" : "+l"(d) : "l"(a), "l"(b));
}
__device__ __forceinline__ float2 unpack2(unsigned long long v) {
    float lo, hi;
    asm("mov.b64 {%0, %1}, %2;" : "=f"(lo), "=f"(hi) : "l"(v));
    return make_float2(lo, hi);
}

// ---------------- int64 width detection ----------------
__global__ void detect64_kernel(const int* p) {
    int odd = p[2 * threadIdx.x + 1];
    unsigned b = __ballot_sync(0xffffffffu, odd == 0);
    if (threadIdx.x == 0) g_src64 = (b == 0xffffffffu) ? 1 : 0;
}

// ---------------- fused projection GEMM (f32x2) ----------------
__global__ __launch_bounds__(256) void proj_gemm4(
    const float* __restrict__ X,
    const float* __restrict__ W0, const float* __restrict__ W1,
    const float* __restrict__ W2, const float* __restrict__ W3,
    float* __restrict__ Y0, float* __restrict__ Y1,
    float* __restrict__ Y2, float* __restrict__ Y3,
    int M)
{
    extern __shared__ float smem[];
    float* xs = smem;             // [128][64]
    float* ws = smem + 128 * 64;  // [64][128]

    const float* W;
    float* Y;
    switch (blockIdx.y) {
        case 0: W = W0; Y = Y0; break;
        case 1: W = W1; Y = Y1; break;
        case 2: W = W2; Y = Y2; break;
        default: W = W3; Y = Y3; break;
    }

    int tid = threadIdx.x;
    int row0 = blockIdx.x * 128;

    #pragma unroll
    for (int i = 0; i < 8; i++) {
        int f4 = tid + i * 256;
        int r = f4 >> 4;
        int k0 = (f4 & 15) << 2;
        float4 v = make_float4(0.f, 0.f, 0.f, 0.f);
        if (row0 + r < M)
            v = *(const float4*)(X + (size_t)(row0 + r) * 64 + k0);
        *(float4*)&xs[r * 64 + k0] = v;
    }
    #pragma unroll
    for (int i = 0; i < 8; i++) {
        int f4 = tid + i * 256;
        int k = f4 >> 5;
        int c = (f4 & 31) << 2;
        *(float4*)&ws[k * 128 + c] = *(const float4*)(W + (size_t)k * 128 + c);
    }
    __syncthreads();

    int tr = tid >> 4, tc = tid & 15;
    int r0 = tr * 8, c0 = tc * 8;

    unsigned long long acc[8][4];
    #pragma unroll
    for (int i = 0; i < 8; i++)
        #pragma unroll
        for (int p = 0; p < 4; p++) acc[i][p] = 0ull;

    #pragma unroll 2
    for (int k0 = 0; k0 < 64; k0 += 4) {
        float4 xq[8];
        #pragma unroll
        for (int i = 0; i < 8; i++)
            xq[i] = *(const float4*)&xs[(r0 + i) * 64 + k0];

        #pragma unroll
        for (int j = 0; j < 4; j++) {
            int k = k0 + j;
            ulonglong2 wv0 = *(const ulonglong2*)&ws[k * 128 + c0];
            ulonglong2 wv1 = *(const ulonglong2*)&ws[k * 128 + c0 + 4];
            #pragma unroll
            for (int i = 0; i < 8; i++) {
                float xv = (j == 0) ? xq[i].x : (j == 1) ? xq[i].y
                         : (j == 2) ? xq[i].z : xq[i].w;
                unsigned long long xx = pack_dup(xv);
                ffma2(acc[i][0], xx, wv0.x);
                ffma2(acc[i][1], xx, wv0.y);
                ffma2(acc[i][2], xx, wv1.x);
                ffma2(acc[i][3], xx, wv1.y);
            }
        }
    }

    #pragma unroll
    for (int i = 0; i < 8; i++) {
        int row = row0 + r0 + i;
        if (row < M) {
            float2 a0 = unpack2(acc[i][0]);
            float2 a1 = unpack2(acc[i][1]);
            float2 a2 = unpack2(acc[i][2]);
            float2 a3 = unpack2(acc[i][3]);
            *(float4*)(Y + (size_t)row * HC + c0)     = make_float4(a0.x, a0.y, a1.x, a1.y);
            *(float4*)(Y + (size_t)row * HC + c0 + 4) = make_float4(a2.x, a2.y, a3.x, a3.y);
        }
    }
}

// ---------------- merged CSR build ----------------
__global__ void hist3_kernel(const int* __restrict__ dst_tt,
                             const int* __restrict__ dst_bt,
                             const int* __restrict__ dst_tb,
                             int* __restrict__ cnt,
                             int E_tt, int E_bt, int E_tb)
{
    int e = blockIdx.x * blockDim.x + threadIdx.x;
    if (e < E_tt) {
        atomicAdd(&cnt[SEG0 + dst_tt[e]], 1);
    } else if (e < E_tt + E_bt) {
        atomicAdd(&cnt[SEG1 + dst_bt[e - E_tt]], 1);
    } else if (e < E_tt + E_bt + E_tb) {
        atomicAdd(&cnt[SEG2 + dst_tb[e - E_tt - E_bt]], 1);
    }
}

__global__ __launch_bounds__(1024) void scan1_kernel(
    const int* __restrict__ cnt, int* __restrict__ rowptr, int* __restrict__ bsums)
{
    __shared__ int sm[1024];
    int i = blockIdx.x * 1024 + threadIdx.x;
    int v = cnt[i];
    sm[threadIdx.x] = v;
    __syncthreads();
    #pragma unroll
    for (int off = 1; off < 1024; off <<= 1) {
        int t = (threadIdx.x >= off) ? sm[threadIdx.x - off] : 0;
        __syncthreads();
        sm[threadIdx.x] += t;
        __syncthreads();
    }
    rowptr[i] = sm[threadIdx.x] - v;
    if (threadIdx.x == 1023) bsums[blockIdx.x] = sm[1023];
}

__global__ __launch_bounds__(1024) void scan2_kernel(int* __restrict__ bsums)
{
    __shared__ int sm[1024];
    int t = threadIdx.x;
    int v = (t < NBLK) ? bsums[t] : 0;
    sm[t] = v;
    __syncthreads();
    #pragma unroll
    for (int off = 1; off < 1024; off <<= 1) {
        int x = (t >= off) ? sm[t - off] : 0;
        __syncthreads();
        sm[t] += x;
        __syncthreads();
    }
    int excl = sm[t] - v;
    int e100 = sm[99];
    int e200 = sm[199];
    int base = (t < 100) ? 0 : (t < 200) ? e100 : e200;
    if (t < NBLK) bsums[t] = excl - base;
}

__global__ void scan3_kernel(int* __restrict__ rowptr, int* __restrict__ cursor,
                             const int* __restrict__ bsums)
{
    int i = blockIdx.x * blockDim.x + threadIdx.x;
    if (i < NPAD) {
        int r = rowptr[i] + bsums[i >> 10];
        rowptr[i] = r;
        cursor[i] = r;
    }
}

__global__ void scatter3_kernel(const int* __restrict__ src_tt, const int* __restrict__ dst_tt,
                                const int* __restrict__ src_bt, const int* __restrict__ dst_bt,
                                const int* __restrict__ src_tb, const int* __restrict__ dst_tb,
                                int* __restrict__ cursor, int* __restrict__ srcs,
                                int E_tt, int E_bt, int E_tb)
{
    int e = blockIdx.x * blockDim.x + threadIdx.x;
    if (e < E_tt) {
        int d = dst_tt[e];
        int s = g_src64 ? src_tt[2 * e] : src_tt[e];
        int pos = atomicAdd(&cursor[SEG0 + d], 1);
        srcs[pos] = s;
    } else if (e < E_tt + E_bt) {
        int ee = e - E_tt;
        int d = dst_bt[ee];
        int pos = atomicAdd(&cursor[SEG1 + d], 1);
        srcs[E_tt + pos] = src_bt[ee];
    } else if (e < E_tt + E_bt + E_tb) {
        int ee = e - E_tt - E_bt;
        int d = dst_tb[ee];
        int pos = atomicAdd(&cursor[SEG2 + d], 1);
        srcs[E_tt + E_bt + pos] = src_tb[ee];
    }
}

// ---------------- GATv2 edge segment (direct exp, unroll-8) ----------------
__device__ __forceinline__ float warp8_sum(float a) {
    a += __shfl_xor_sync(0xffffffffu, a, 4);
    a += __shfl_xor_sync(0xffffffffu, a, 2);
    a += __shfl_xor_sync(0xffffffffu, a, 1);
    return a;
}
__device__ __forceinline__ float alpha_dot(float4 v, float4 xr4, float4 at4) {
    float m, a = 0.f;
    m = v.x + xr4.x; a += fmaxf(m, NEG_SLOPE * m) * at4.x;
    m = v.y + xr4.y; a += fmaxf(m, NEG_SLOPE * m) * at4.y;
    m = v.z + xr4.z; a += fmaxf(m, NEG_SLOPE * m) * at4.z;
    m = v.w + xr4.w; a += fmaxf(m, NEG_SLOPE * m) * at4.w;
    return a;
}

__device__ __forceinline__ float4 gat_segment(
    const float* __restrict__ xl, float4 xr4, float4 at4,
    const int* __restrict__ srcs, int beg, int end, int co)
{
    float  den = 0.f;
    float4 acc = make_float4(0.f, 0.f, 0.f, 0.f);

    int i = beg;
    for (; i + 7 < end; i += 8) {
        int s[8];
        #pragma unroll
        for (int j = 0; j < 8; j++) s[j] = __ldg(srcs + i + j);
        float4 v[8];
        #pragma unroll
        for (int j = 0; j < 8; j++)
            v[j] = *(const float4*)(xl + (size_t)s[j] * HC + co);
        float a[8];
        #pragma unroll
        for (int j = 0; j < 8; j++) a[j] = alpha_dot(v[j], xr4, at4);
        #pragma unroll
        for (int j = 0; j < 8; j++) a[j] = warp8_sum(a[j]);
        #pragma unroll
        for (int j = 0; j < 8; j++) {
            float p = __expf(a[j]);
            den   += p;
            acc.x += p * v[j].x;
            acc.y += p * v[j].y;
            acc.z += p * v[j].z;
            acc.w += p * v[j].w;
        }
    }
    for (; i < end; i++) {
        int s = __ldg(srcs + i);
        float4 v = *(const float4*)(xl + (size_t)s * HC + co);
        float a = warp8_sum(alpha_dot(v, xr4, at4));
        float p = __expf(a);
        den   += p;
        acc.x += p * v.x;
        acc.y += p * v.y;
        acc.z += p * v.z;
        acc.w += p * v.w;
    }

    float w = 1.f / (den + 1e-16f);
    return make_float4(acc.x * w, acc.y * w, acc.z * w, acc.w * w);
}

// ---------------- fused tx conv ----------------
__global__ __launch_bounds__(256) void gat_conv_tx_kernel(
    const float* __restrict__ xl_tt, const float* __restrict__ xr_tt,
    const float* __restrict__ att_tt, const float* __restrict__ b_tt,
    const float* __restrict__ xl_bt, const float* __restrict__ xr_bt,
    const float* __restrict__ att_bt, const float* __restrict__ b_bt,
    const int* __restrict__ rowptr, const int* __restrict__ srcs,
    int E_tt, float* __restrict__ out, int n_dst)
{
    int d = (blockIdx.x * blockDim.x + threadIdx.x) >> 5;
    if (d >= n_dst) return;
    int lane = threadIdx.x & 31;
    int co = lane * 4;

    int beg1 = rowptr[SEG0 + d];
    int end1 = rowptr[SEG0 + d + 1];
    float4 xr1 = *(const float4*)(xr_tt + (size_t)d * HC + co);
    float4 at1 = *(const float4*)(att_tt + co);
    float4 r1 = gat_segment(xl_tt, xr1, at1, srcs, beg1, end1, co);

    int beg2 = rowptr[SEG1 + d];
    int end2 = rowptr[SEG1 + d + 1];
    float4 xr2 = *(const float4*)(xr_bt + (size_t)d * HC + co);
    float4 at2 = *(const float4*)(att_bt + co);
    float4 r2 = gat_segment(xl_bt, xr2, at2, srcs + E_tt, beg2, end2, co);

    float4 bb1 = *(const float4*)(b_tt + co);
    float4 bb2 = *(const float4*)(b_bt + co);

    float4 o;
    o.x = r1.x + r2.x + bb1.x + bb2.x;
    o.y = r1.y + r2.y + bb1.y + bb2.y;
    o.z = r1.z + r2.z + bb1.z + bb2.z;
    o.w = r1.w + r2.w + bb1.w + bb2.w;
    *(float4*)(out + (size_t)d * HC + co) = o;
}

// ---------------- bd conv ----------------
__global__ __launch_bounds__(256) void gat_conv_bd_kernel(
    const float* __restrict__ xl, const float* __restrict__ xr,
    const float* __restrict__ att, const float* __restrict__ bias,
    const int* __restrict__ rowptr, const int* __restrict__ srcs,
    float* __restrict__ out, int n_dst)
{
    int d = (blockIdx.x * blockDim.x + threadIdx.x) >> 5;
    if (d >= n_dst) return;
    int lane = threadIdx.x & 31;
    int co = lane * 4;

    int beg = rowptr[SEG2 + d];
    int end = rowptr[SEG2 + d + 1];
    float4 xr4 = *(const float4*)(xr + (size_t)d * HC + co);
    float4 at4 = *(const float4*)(att + co);
    float4 r = gat_segment(xl, xr4, at4, srcs, beg, end, co);

    float4 bb = *(const float4*)(bias + co);
    *(float4*)(out + (size_t)d * HC + co) =
        make_float4(r.x + bb.x, r.y + bb.y, r.z + bb.z, r.w + bb.w);
}

// ---------------- host orchestration ----------------
static inline int divup(int a, int b) { return (a + b - 1) / b; }

extern "C" void kernel_launch(void* const* d_in, const int* in_sizes, int n_in,
                              void* d_out, int out_size)
{
    const float* x_tx = (const float*)d_in[0];
    const float* x_bd = (const float*)d_in[1];
    const int* src_tt = (const int*)d_in[2];
    const int* dst_tt = (const int*)d_in[3];
    const int* src_tb = (const int*)d_in[4];
    const int* dst_tb = (const int*)d_in[5];
    const int* src_bt = (const int*)d_in[6];
    const int* dst_bt = (const int*)d_in[7];
    const float* Wl_tt = (const float*)d_in[8];
    const float* Wr_tt = (const float*)d_in[9];
    const float* att_tt = (const float*)d_in[10];
    const float* b_tt  = (const float*)d_in[11];
    const float* Wl_tb = (const float*)d_in[12];
    const float* Wr_tb = (const float*)d_in[13];
    const float* att_tb = (const float*)d_in[14];
    const float* b_tb  = (const float*)d_in[15];
    const float* Wl_bt = (const float*)d_in[16];
    const float* Wr_bt = (const float*)d_in[17];
    const float* att_bt = (const float*)d_in[18];
    const float* b_bt  = (const float*)d_in[19];

    float* out = (float*)d_out;

    int n_tx = in_sizes[0] / 64;
    int n_bd = in_sizes[1] / 64;
    int E_tt = in_sizes[3];
    int E_tb = in_sizes[5];
    int E_bt = in_sizes[7];
    int E_all = E_tt + E_bt + E_tb;

    float *xl_tt, *xr_tt, *xl_tb, *xr_bt, *xl_bt, *xr_tb;
    int *cnt, *rowptr, *cursor, *bsums, *srcs;
    cudaGetSymbolAddress((void**)&xl_tt, g_xl_tt);
    cudaGetSymbolAddress((void**)&xr_tt, g_xr_tt);
    cudaGetSymbolAddress((void**)&xl_tb, g_xl_tb);
    cudaGetSymbolAddress((void**)&xr_bt, g_xr_bt);
    cudaGetSymbolAddress((void**)&xl_bt, g_xl_bt);
    cudaGetSymbolAddress((void**)&xr_tb, g_xr_tb);
    cudaGetSymbolAddress((void**)&cnt,    g_cnt);
    cudaGetSymbolAddress((void**)&rowptr, g_rowptr);
    cudaGetSymbolAddress((void**)&cursor, g_cursor);
    cudaGetSymbolAddress((void**)&bsums,  g_bsums);
    cudaGetSymbolAddress((void**)&srcs,   g_srcs);

    const int SMEM = (128 * 64 + 64 * 128) * (int)sizeof(float);
    cudaFuncSetAttribute(proj_gemm4, cudaFuncAttributeMaxDynamicSharedMemorySize, SMEM);

    const bool fork = g_fork.ok;
    cudaStream_t sproj = fork ? g_fork.s1 : (cudaStream_t)0;

    // ---- fork: projections on side stream, CSR build on main stream ----
    if (fork) {
        cudaEventRecord(g_fork.e0, 0);
        cudaStreamWaitEvent(g_fork.s1, g_fork.e0, 0);
    }

    dim3 gtx(divup(n_tx, 128), 4);
    proj_gemm4<<<gtx, 256, SMEM, sproj>>>(x_tx,
        Wl_tt, Wr_tt, Wl_tb, Wr_bt,
        xl_tt, xr_tt, xl_tb, xr_bt, n_tx);
    dim3 gbd(divup(n_bd, 128), 2);
    proj_gemm4<<<gbd, 256, SMEM, sproj>>>(x_bd,
        Wl_bt, Wr_tb, Wl_bt, Wr_tb,
        xl_bt, xr_tb, xl_bt, xr_tb, n_bd);
    if (fork) cudaEventRecord(g_fork.e1, g_fork.s1);

    // main stream: CSR build
    detect64_kernel<<<1, 32>>>(src_tt);
    cudaMemsetAsync(cnt, 0, NPAD * sizeof(int));
    hist3_kernel<<<divup(E_all, 256), 256>>>(dst_tt, dst_bt, dst_tb, cnt, E_tt, E_bt, E_tb);
    scan1_kernel<<<NBLK, 1024>>>(cnt, rowptr, bsums);
    scan2_kernel<<<1, 1024>>>(bsums);
    scan3_kernel<<<divup(NPAD, 256), 256>>>(rowptr, cursor, bsums);
    scatter3_kernel<<<divup(E_all, 256), 256>>>(src_tt, dst_tt, src_bt, dst_bt,
                                                src_tb, dst_tb, cursor, srcs,
                                                E_tt, E_bt, E_tb);

    // join
    if (fork) cudaStreamWaitEvent(0, g_fork.e1, 0);

    // ---- convolutions ----
    gat_conv_tx_kernel<<<divup(n_tx * 32, 256), 256>>>(
        xl_tt, xr_tt, att_tt, b_tt,
        xl_bt, xr_bt, att_bt, b_bt,
        rowptr, srcs, E_tt, out, n_tx);

    gat_conv_bd_kernel<<<divup(n_bd * 32, 256), 256>>>(
        xl_tb, xr_tb, att_tb, b_tb,
        rowptr, srcs + E_tt + E_bt, out + (size_t)n_tx * HC, n_bd);
}